// round 5
// baseline (speedup 1.0000x reference)
#include <cuda_runtime.h>
#include <cstdint>

// BiLIF: out[t] = (s1[t] + s2[t]) / 2
//   s1 = LIF(x,       tau=1/0.75, v_th=0.75)   forward in t
//   s2 = LIF(flip(x), tau=1/0.75, v_th=1.25)   reversed input, NOT flipped back
// LIF step: h = 0.25*v + 0.75*x ; s = (h >= v_th) ; v = s ? 0 : h
//
// R3 postmortem: register-resident series (float2/thread, 60 regs) caps occ at
// 41.8%, DRAM 74.7%. This version stages the T=16 series in SHARED memory via
// cp.async (no register staging), dropping regs to ~30. smem 32KB/block ->
// ~7 blocks/SM -> ~87% occupancy target. smem bandwidth is not binding
// (~47us of crossbar time vs ~79us DRAM time chip-wide).
// (R4 was an infra failure; this is a resubmission of the same design.)

constexpr int T = 16;
constexpr int THREADS = 256;
constexpr int ELEMS = THREADS * 2;             // 512 floats per block per timestep
constexpr int CHUNKS_PER_ROW = ELEMS * 4 / 16; // 128 x 16B chunks per row
constexpr int CHUNKS_PER_THREAD = T * CHUNKS_PER_ROW / THREADS; // 8

__global__ __launch_bounds__(THREADS)
void bilif_kernel(const float* __restrict__ x,
                  float2* __restrict__ out2,
                  int per_t)                    // floats per time step (B*N)
{
    __shared__ float sm[T][ELEMS];              // 32 KB

    const int tid = threadIdx.x;
    const long long base = (long long)blockIdx.x * ELEMS;  // float offset in a row

    // ---- gmem -> smem via cp.async.cg 16B (no register staging) ----
    // chunk index c*256+tid: rows have 128 chunks, so each warp's 32 chunks sit
    // inside one t-row (512B contiguous gmem per warp, conflict-free STS), and
    // consecutive c values step t by 2 -> loads spread across all 16 rows.
    uint32_t s_base = (uint32_t)__cvta_generic_to_shared(&sm[0][0]);
#pragma unroll
    for (int c = 0; c < CHUNKS_PER_THREAD; ++c) {
        int chunk = c * THREADS + tid;
        int t   = chunk >> 7;                   // / CHUNKS_PER_ROW
        int off = chunk & (CHUNKS_PER_ROW - 1); // 16B units within row
        const float* src = x + (long long)t * per_t + base + off * 4;
        uint32_t dst = s_base + (uint32_t)(t * ELEMS + off * 4) * 4u;
        asm volatile("cp.async.cg.shared.global [%0], [%1], 16;\n"
                     :: "r"(dst), "l"(src));
    }
    asm volatile("cp.async.commit_group;\n");
    asm volatile("cp.async.wait_group 0;\n");
    __syncthreads();

    // ---- forward scan: spike bits -> per-neuron masks, v_th = 0.75 ----
    float v0 = 0.f, v1 = 0.f;
    unsigned m0 = 0u, m1 = 0u;
#pragma unroll
    for (int t = 0; t < T; ++t) {
        float x0 = sm[t][2 * tid];
        float x1 = sm[t][2 * tid + 1];          // LDS.64, conflict-free
        float h0 = fmaf(0.25f, v0, 0.75f * x0);
        float h1 = fmaf(0.25f, v1, 0.75f * x1);
        bool s0 = (h0 >= 0.75f);
        bool s1 = (h1 >= 0.75f);
        m0 |= (unsigned)s0 << t;
        m1 |= (unsigned)s1 << t;
        v0 = s0 ? 0.f : h0;
        v1 = s1 ? 0.f : h1;
    }

    // ---- backward scan on reversed input, v_th = 1.25; fused output ----
    v0 = 0.f; v1 = 0.f;
    const long long obase = base >> 1;          // float2 offset within a row
    const int s2len = per_t >> 1;               // float2 per time step
#pragma unroll
    for (int k = 0; k < T; ++k) {
        const int t = T - 1 - k;                // rev[k] = x[T-1-k]
        float x0 = sm[t][2 * tid];
        float x1 = sm[t][2 * tid + 1];
        float h0 = fmaf(0.25f, v0, 0.75f * x0);
        float h1 = fmaf(0.25f, v1, 0.75f * x1);
        bool s0 = (h0 >= 1.25f);
        bool s1 = (h1 >= 1.25f);
        v0 = s0 ? 0.f : h0;
        v1 = s1 ? 0.f : h1;
        // o = 0.5*bit + 0.5*s, via predicate selects (no int->float cvt)
        float b0 = (m0 & (1u << k)) ? 0.5f : 0.0f;
        float b1 = (m1 & (1u << k)) ? 0.5f : 0.0f;
        float2 o;
        o.x = s0 ? b0 + 0.5f : b0;
        o.y = s1 ? b1 + 0.5f : b1;
        __stcs(&out2[(long long)k * s2len + obase + tid], o);
    }
}

extern "C" void kernel_launch(void* const* d_in, const int* in_sizes, int n_in,
                              void* d_out, int out_size)
{
    const float* x = (const float*)d_in[0];
    float* out = (float*)d_out;

    const int total = in_sizes[0];          // T * B * N = 67,108,864
    const int per_t = total / T;            // B * N = 4,194,304

    const int blocks = per_t / ELEMS;       // 8192
    bilif_kernel<<<blocks, THREADS>>>(x, (float2*)out, per_t);
}